// round 6
// baseline (speedup 1.0000x reference)
#include <cuda_runtime.h>
#include <math.h>

// Problem constants (fixed by the dataset)
#define B_ 4
#define S_ 256
#define E_ 256
#define H_ 128
#define N_ (B_ * S_)   // 1024 rows total

// Scratch (static device arrays; allocation-free per harness rules)
__device__ float g_ampq[N_ * E_];
__device__ float g_ampk[N_ * E_];
__device__ float g_V[N_ * H_];
__device__ float g_Pq[N_ * E_];            // row-major, query side
__device__ float g_PkT[B_ * E_ * S_];      // TRANSPOSED: [b][e][j], key side
__device__ float g_entq[N_];               // sum_e P * lg2(P + 1e-10)
__device__ float g_entk[N_];

// ---- packed f32x2 helpers (sm_100a) ---------------------------------------
__device__ __forceinline__ unsigned long long pk2(float lo, float hi) {
    unsigned long long r;
    asm("mov.b64 %0, {%1, %2};" : "=l"(r) : "f"(lo), "f"(hi));
    return r;
}
__device__ __forceinline__ float2 unpk2(unsigned long long p) {
    float2 r;
    asm("mov.b64 {%0, %1}, %2;" : "=f"(r.x), "=f"(r.y) : "l"(p));
    return r;
}
__device__ __forceinline__ void ffma2(unsigned long long& acc,
                                      unsigned long long a,
                                      unsigned long long b) {
    asm("fma.rn.f32x2 %0, %1, %2, %0;" : "+l"(acc) : "l"(a), "l"(b));
}

// ---------------------------------------------------------------------------
// Kernel 1: C[1024, 640] = x[1024,256] @ [Wq;Wk;Wv]^T   (region per f-tile)
// 32x64 CTA tile, 256 threads, 2x4 micro-tile with packed fma.rn.f32x2.
// Grid = 320 CTAs -> ~17 warps/SM (vs 8 before); FMA-pipe floor halved.
// ---------------------------------------------------------------------------
__global__ __launch_bounds__(256) void k1_gemm(
    const float* __restrict__ x,
    const float* __restrict__ Wq,
    const float* __restrict__ Wk,
    const float* __restrict__ Wv)
{
    __shared__ __align__(16) float As[32][34];  // [k][m], stride 34 (8B-aligned rows)
    __shared__ __align__(16) float Bs[32][68];  // [k][f], stride 68 (16B-aligned rows)

    const int m0 = blockIdx.x * 32;       // row tile (0..31)
    const int f0 = blockIdx.y * 64;       // f tile (0..9) over concat 640

    const float* Wp; float* outp; int fo, ostride;
    if (f0 < 256)      { Wp = Wq; fo = f0;       outp = g_ampq; ostride = E_; }
    else if (f0 < 512) { Wp = Wk; fo = f0 - 256; outp = g_ampk; ostride = E_; }
    else               { Wp = Wv; fo = f0 - 512; outp = g_V;    ostride = H_; }

    const int tid = threadIdx.x;
    const int tx  = tid & 15;             // f micro (4 cols)
    const int ty  = tid >> 4;             // m micro (2 rows), 0..15

    // Loader mapping (coalesced LDG)
    const int arow = tid >> 3;            // 0..31
    const int ak   = (tid & 7) * 4;       // 4 floats
    const int brow = tid >> 2;            // 0..63
    const int bk   = (tid & 3) * 8;       // 8 floats

    const float* xg = x  + (m0 + arow) * E_ + ak;
    const float* wg = Wp + (fo + brow) * E_ + bk;

    unsigned long long c00 = 0ull, c01 = 0ull, c10 = 0ull, c11 = 0ull;

    for (int k0 = 0; k0 < E_; k0 += 32) {
        float4 a4 = *(const float4*)(xg + k0);
        float4 b0 = *(const float4*)(wg + k0);
        float4 b1 = *(const float4*)(wg + k0 + 4);
        As[ak+0][arow] = a4.x; As[ak+1][arow] = a4.y;
        As[ak+2][arow] = a4.z; As[ak+3][arow] = a4.w;
        Bs[bk+0][brow] = b0.x; Bs[bk+1][brow] = b0.y;
        Bs[bk+2][brow] = b0.z; Bs[bk+3][brow] = b0.w;
        Bs[bk+4][brow] = b1.x; Bs[bk+5][brow] = b1.y;
        Bs[bk+6][brow] = b1.z; Bs[bk+7][brow] = b1.w;
        __syncthreads();

        #pragma unroll
        for (int kk = 0; kk < 32; kk++) {
            float2 av = *(const float2*)&As[kk][ty * 2];
            float4 bv = *(const float4*)&Bs[kk][tx * 4];
            unsigned long long pa0  = pk2(av.x, av.x);
            unsigned long long pa1  = pk2(av.y, av.y);
            unsigned long long pb01 = pk2(bv.x, bv.y);
            unsigned long long pb23 = pk2(bv.z, bv.w);
            ffma2(c00, pa0, pb01);
            ffma2(c01, pa0, pb23);
            ffma2(c10, pa1, pb01);
            ffma2(c11, pa1, pb23);
        }
        __syncthreads();
    }

    float2 u00 = unpk2(c00), u01 = unpk2(c01);
    float2 u10 = unpk2(c10), u11 = unpk2(c11);
    const int r0 = m0 + ty * 2;
    *(float4*)&outp[ r0      * ostride + fo + tx * 4] =
        make_float4(u00.x, u00.y, u01.x, u01.y);
    *(float4*)&outp[(r0 + 1) * ostride + fo + tx * 4] =
        make_float4(u10.x, u10.y, u11.x, u11.y);
}

// ---------------------------------------------------------------------------
// Kernel 2: warp-per-row probs + entropy.  Each warp owns one (row, region):
// P = amp^2 / (ssq_amp + EPS*d^2), d = ||x_n|| + 1e-12 (psi-norm folded in),
// ent = sum P*lg2(P+EPS).  Warp-only shfl butterflies (no __syncthreads).
// Query side stores row-major g_Pq; key side stores TRANSPOSED g_PkT[b][e][j].
// grid 256 CTAs x 256 threads (8 warps = 8 row-slots each).
// ---------------------------------------------------------------------------
__global__ __launch_bounds__(256) void k2_probs(const float* __restrict__ x)
{
    const int w    = threadIdx.x >> 5;
    const int lane = threadIdx.x & 31;
    const int slot = blockIdx.x * 8 + w;       // 0..2047
    const int regn = slot >> 10;               // 0 = q, 1 = k
    const int n    = slot & 1023;
    const int b    = n >> 8;
    const int j    = n & 255;

    const float* amp = (regn ? g_ampk : g_ampq) + n * E_;
    const float* xr  = x + n * E_;

    float a[8];
    float ssa = 0.f, ssx = 0.f;
    #pragma unroll
    for (int m = 0; m < 8; m++) {
        a[m] = amp[lane + 32 * m];
        float xv = xr[lane + 32 * m];
        ssa = fmaf(a[m], a[m], ssa);
        ssx = fmaf(xv, xv, ssx);
    }
    #pragma unroll
    for (int o = 16; o; o >>= 1) {
        ssa += __shfl_xor_sync(0xffffffffu, ssa, o);
        ssx += __shfl_xor_sync(0xffffffffu, ssx, o);
    }
    const float d   = sqrtf(ssx) + 1e-12f;
    const float inv = 1.0f / (ssa + 1e-10f * d * d);

    float ent = 0.f;
    #pragma unroll
    for (int m = 0; m < 8; m++) {
        const float P = a[m] * a[m] * inv;
        ent = fmaf(P, __log2f(P + 1e-10f), ent);
        if (regn) g_PkT[b * (E_ * S_) + (lane + 32 * m) * S_ + j] = P;
        else      g_Pq [n * E_ + lane + 32 * m] = P;
    }
    #pragma unroll
    for (int o = 16; o; o >>= 1)
        ent += __shfl_xor_sync(0xffffffffu, ent, o);
    if (lane == 0) (regn ? g_entk : g_entq)[n] = ent;
}

// ---------------------------------------------------------------------------
// Kernel 3: fused JS score + causal row-normalize + attn @ V.
// One CTA handles query rows (i0, i1 = i0+1).  Lane l of warp w owns key
// column j = 32*w + l; it serially accumulates over e with coalesced loads
// from transposed g_PkT -- NO per-j shuffle reduction at all.  Causality is
// exploited by skipping whole warps with jbase > i1.  MUFU(lg2)-bound.
// ---------------------------------------------------------------------------
__global__ __launch_bounds__(256) void k3_attn(float* __restrict__ out)
{
    __shared__ float2 sPi[256];        // (P_i0[e], P_i1[e]) interleaved
    __shared__ float sScore[2][256];
    __shared__ float sO[2][128];
    __shared__ float sred[2][8];
    __shared__ float sInv[2];

    const int c  = blockIdx.x;        // 0..511
    const int n0 = c * 2;
    const int b  = n0 >> 8;
    const int i0 = n0 & 255;
    const int i1 = i0 + 1;
    const int tid  = threadIdx.x;
    const int w    = tid >> 5;
    const int lane = tid & 31;

    // Stage both query P rows into smem (coalesced), interleaved for LDS.64.
    const float* Pq = g_Pq + n0 * E_;
    sPi[tid] = make_float2(Pq[tid], Pq[E_ + tid]);
    const float hq0 = g_entq[n0];
    const float hq1 = g_entq[n0 + 1];
    __syncthreads();

    const int jb = w * 32;
    if (jb <= i1) {
        const int j = jb + lane;
        const float* qp = g_PkT + b * (E_ * S_) + j;
        float acc0 = 0.f, acc1 = 0.f;
        #pragma unroll 8
        for (int e = 0; e < E_; e++) {
            const float  q  = qp[e * S_];          // coalesced 128B / warp
            const float2 pi = sPi[e];              // broadcast
            const float  s0 = pi.x + q;
            const float  s1 = pi.y + q;
            acc0 = fmaf(s0, __log2f(fmaf(0.5f, s0, 1e-10f)), acc0);
            acc1 = fmaf(s1, __log2f(fmaf(0.5f, s1, 1e-10f)), acc1);
        }
        const float HL = 0.34657359028f;           // 0.5 * ln(2)
        const float hk  = g_entk[b * S_ + j];
        const float js0 = HL * (hq0 + hk - acc0);
        const float js1 = HL * (hq1 + hk - acc1);
        sScore[0][j] = (j <= i0) ? (1.0f - js0) : 0.0f;
        sScore[1][j] = (j <= i1) ? (1.0f - js1) : 0.0f;
    }
    __syncthreads();

    // Row L1-normalization sums (only j<=i entries are ever read).
    float v0 = (tid <= i0) ? fabsf(sScore[0][tid]) : 0.f;
    float v1 = (tid <= i1) ? fabsf(sScore[1][tid]) : 0.f;
    #pragma unroll
    for (int o = 16; o; o >>= 1) {
        v0 += __shfl_xor_sync(0xffffffffu, v0, o);
        v1 += __shfl_xor_sync(0xffffffffu, v1, o);
    }
    if (lane == 0) { sred[0][w] = v0; sred[1][w] = v1; }
    __syncthreads();
    if (tid == 0) {
        float s0 = 0.f, s1 = 0.f;
        #pragma unroll
        for (int k = 0; k < 8; k++) { s0 += sred[0][k]; s1 += sred[1][k]; }
        sInv[0] = 1.0f / fmaxf(s0, 1e-12f);
        sInv[1] = 1.0f / fmaxf(s1, 1e-12f);
    }
    __syncthreads();

    // out[i,h] = inv * sum_{j<=i} score[j] * V[j,h]; split j over 2 halves.
    const int half = tid >> 7;
    const int h    = tid & 127;
    const float* Vb = g_V + b * S_ * H_;
    float a0 = 0.f, a1 = 0.f;
    for (int j = half; j <= i1; j += 2) {
        float v = Vb[j * H_ + h];
        a0 = fmaf(sScore[0][j], v, a0);   // sScore[0][i1] == 0 (masked)
        a1 = fmaf(sScore[1][j], v, a1);
    }
    if (half == 1) { sO[0][h] = a0; sO[1][h] = a1; }
    __syncthreads();
    if (half == 0) {
        out[n0 * H_ + h]       = (a0 + sO[0][h]) * sInv[0];
        out[(n0 + 1) * H_ + h] = (a1 + sO[1][h]) * sInv[1];
    }
}

// ---------------------------------------------------------------------------
// Launch. Inputs per metadata order: x, Wv, Wq, Wk (all float32).
// ---------------------------------------------------------------------------
extern "C" void kernel_launch(void* const* d_in, const int* in_sizes, int n_in,
                              void* d_out, int out_size)
{
    const float* x  = (const float*)d_in[0];
    const float* Wv = (const float*)d_in[1];
    const float* Wq = (const float*)d_in[2];
    const float* Wk = (const float*)d_in[3];
    float* out = (float*)d_out;

    k1_gemm<<<dim3(32, 10), 256>>>(x, Wq, Wk, Wv);
    k2_probs<<<256, 256>>>(x);
    k3_attn<<<512, 256>>>(out);
}